// round 8
// baseline (speedup 1.0000x reference)
#include <cuda_runtime.h>

// BWSGODE: 8192-step serial scalar ODE, single-thread issue-bound.
//
// v8 = v7 (bit-exact producer loop + SMSP-0-isolated consumers) + fine-
// grained publishing of the FINAL 512 rows (128-row boundaries) + fast
// (32ns) consumer polling in the fine region. Rationale: the loop sits at
// its validated hard floor (14 fma-pipe ops x rt=2 = 28 cyc/iter); the only
// recoverable time left is the post-loop tail (last-chunk copy + sleep-
// quantum discovery latency).
//
// Boundary schedule (identical on producer & consumers):
//   512-row steps up to fine_start = max(0, num_steps-512), then 128-row
//   steps to num_steps. All boundaries are multiples of 128 -> row*5/4 is
//   integral, so chunk copies stay pure STG.128.

__device__ __forceinline__ int next_boundary(int cur, int num_steps,
                                             int fine_start) {
    if (cur < fine_start) {
        int nb = (cur & ~511) + 512;
        return (nb > fine_start) ? fine_start : nb;
    }
    int nb = fine_start + ((((cur - fine_start) >> 7) + 1) << 7);
    return (nb > num_steps) ? num_steps : nb;
}

__shared__ volatile int s_progress;

__global__ void __launch_bounds__(256, 1)
bwsg_ode_kernel(const float* __restrict__ y0,
                const float* __restrict__ p,
                float* __restrict__ out,
                int num_steps) {
    extern __shared__ float4 traj[];  // num_steps entries (128 KB @ 8192)

    const int tid = threadIdx.x;
    const int wid = tid >> 5;
    if (tid == 0) s_progress = 0;
    __syncthreads();  // the ONLY block-wide sync; everything after is P/C.

    const float iv = __ldg(&y0[4]);
    const int fine_start = (num_steps > 512) ? (num_steps - 512) : 0;

    if (tid == 0) {
        // ---------------- producer: the serial recurrence ----------------
        float B = __ldg(&y0[0]);
        float W = __ldg(&y0[1]);
        float S = __ldg(&y0[2]);
        float G = __ldg(&y0[3]);

        const float p0 = p[0], p2 = p[2], p5 = p[5], p8 = p[8];
        const float np1 = -p[1], np3 = -p[3], np4 = -p[4];
        const float np6 = -p[6], np7 = -p[7], np9 = -p[9];
        const float np0 = -p0;

        const float fi  = (iv != 0.0f) ? 1.0f : 0.0f;
        const float thr = __fsub_rn(__fadd_rn(5.0f, iv), 1.0f);

        // First integer step with mask==1 (j >= thr <=> j >= ceil(thr) for
        // integer j; fp compare of exact integers is exact).
        int j0 = 1;
        if (fi != 0.0f) {
            float ct = ceilf(thr);
            if (ct > 1.0f) {
                j0 = (ct >= (float)num_steps) ? num_steps : (int)ct;
            }
        }

        traj[0] = make_float4(B, W, S, G);

        // ---- Phase 1: mask == 0 (interventional only), B frozen ----
        for (int j = 1; j < j0; ++j) {
            float a = __fmaf_rn(np0, G, p0);
            a       = __fmaf_rn(np1, S, a);
            float c = __fmaf_rn(p2, G, np4);
            float b = __fmaf_rn(np3, W, c);
            float d = __fmaf_rn(p5, S, np7);
            float e = __fmul_rn(W, d);
            float nS = __fmaf_rn(b, S, S);
            float nW = __fmaf_rn(e, W, W);
            float nG = __fmaf_rn(a, G, G);
            W = nW; S = nS; G = nG;
            traj[j] = make_float4(B, W, S, G);
        }

        // ---- Phase 2: mask == 1 hot loop (14 fp ops), chunk-published ----
        int j = j0;
        while (j < num_steps) {
            const int end = next_boundary(j, num_steps, fine_start);
            #pragma unroll 8
            for (; j < end; ++j) {
                float a = __fmaf_rn(np0, G, p0);     // p0 - p0*G
                a       = __fmaf_rn(np1, S, a);      //   - p1*S
                float t = __fadd_rn(W, B);           // W + B
                float c = __fmaf_rn(p2, G, np4);     // p2*G - p4
                float b = __fmaf_rn(np3, t, c);      //   - p3*(W+B)
                float d = __fmaf_rn(p5, S, np7);     // p5*S - p7
                d       = __fmaf_rn(np6, B, d);      //   - p6*B
                float e = __fmul_rn(W, d);           // W*(...)
                float f = __fadd_rn(S, W);           // S + W
                float g = __fmaf_rn(p8, f, np9);     // p8*(S+W) - p9
                float nB = __fmaf_rn(g, B, B);
                float nW = __fmaf_rn(e, W, W);
                float nS = __fmaf_rn(b, S, S);
                float nG = __fmaf_rn(a, G, G);
                B = nB; W = nW; S = nS; G = nG;
                traj[j] = make_float4(B, W, S, G);   // STS.128 (hidden)
            }
            __threadfence_block();
            s_progress = end;
        }
        __threadfence_block();
        s_progress = num_steps;  // covers j0 == num_steps
    } else if (wid != 4 && tid >= 32) {
        // ------- consumers: warps 1,2,3,5,6,7 (SMSP 0 kept clear) --------
        const int ct  = (wid < 4) ? (tid - 32) : (tid - 64);  // 0..191
        const int ncs = 192;
        const float* tf = (const float*)traj;       // flat smem floats
        float4* o4 = (float4*)out;

        const int total_f  = num_steps * 5;
        const int total_f4 = total_f >> 2;

        int b = 0;
        while (b < num_steps) {
            const int nb = next_boundary(b, num_steps, fine_start);
            const int slp = (nb > fine_start) ? 32 : 256;
            while (s_progress < nb) __nanosleep(slp);
            __threadfence_block();  // acquire: traj data before flag

            const int m0 = (b * 5) >> 2;           // b multiple of 128
            int m1 = (nb * 5) >> 2;
            if (m1 > total_f4) m1 = total_f4;
            for (int m = m0 + ct; m < m1; m += ncs) {
                const int n = m << 2;
                float v[4];
                #pragma unroll
                for (int e = 0; e < 4; ++e) {
                    const int ne = n + e;
                    const int r  = ne / 5;
                    const int c  = ne - r * 5;
                    v[e] = (c == 4) ? iv : tf[(r << 2) + c];
                }
                o4[m] = make_float4(v[0], v[1], v[2], v[3]);  // STG.128
            }
            b = nb;
        }
        // scalar tail if num_steps*5 % 4 != 0 (not hit at 8192, kept general)
        if (ct == 0) {
            for (int ne = total_f4 << 2; ne < total_f; ++ne) {
                const int r = ne / 5;
                const int c = ne - r * 5;
                out[ne] = (c == 4) ? iv : tf[(r << 2) + c];
            }
        }
    }
    // warp 0 lanes 1..31 and all of warp 4: fall through and exit,
    // leaving SMSP 0's issue slots to the producer.
}

extern "C" void kernel_launch(void* const* d_in, const int* in_sizes, int n_in,
                              void* d_out, int out_size) {
    const float* y0     = (const float*)d_in[0];
    const float* params = (const float*)d_in[1];
    const int num_steps = out_size / 5;

    const size_t smem = (size_t)num_steps * sizeof(float4);
    cudaFuncSetAttribute(bwsg_ode_kernel,
                         cudaFuncAttributeMaxDynamicSharedMemorySize,
                         (int)smem);
    bwsg_ode_kernel<<<1, 256, smem>>>(y0, params, (float*)d_out, num_steps);
}